// round 15
// baseline (speedup 1.0000x reference)
#include <cuda_runtime.h>
#include <cuda_fp16.h>
#include <cstdint>

#define NMAX 1048576
#define EMAX 4194304
#define DD   32
#define RR   4
#define HIST_CHUNK 4096
#define MAXBLK (EMAX / HIST_CHUNK)   // 1024

// Node feature arrays use "layout L": within a 32-half row, position
// j = 8q + 2m + odd holds feature f = 2q + 8m + odd  (q,m in 0..3).
__device__ __half g_h16[(size_t)NMAX * DD];          // 64 MB layer-1 input (layout L)
__device__ __half g_aggA[(size_t)(NMAX + 16) * DD];  // 64 MB (+dummy rows, layout L)
__device__ __half g_aggB[(size_t)(NMAX + 16) * DD];  // 64 MB (+dummy rows, layout L)
__device__ int2   g_bedge[EMAX + 64];                // edges binned by etype: (src, dst)
__device__ int    g_bh[MAXBLK * RR];
__device__ int    g_bb[MAXBLK * RR];
__device__ int    g_meta[4];                         // bin ends (16-aligned)

// ---------------------------------------------------------------------------
__device__ __forceinline__ unsigned pack_h2(float a, float b) {
    __half2 h = __floats2half2_rn(a, b);
    return *reinterpret_cast<unsigned*>(&h);
}
__device__ __forceinline__ unsigned relu_u(unsigned v) {
    __half2 h = *reinterpret_cast<__half2*>(&v);
    h = __hmax2(h, __float2half2_rn(0.0f));
    return *reinterpret_cast<unsigned*>(&h);
}
#define RED16(ptr, r0, r1, r2, r3)                                             \
    asm volatile("red.global.add.noftz.v4.f16x2 [%0], {%1, %2, %3, %4};"      \
                 :: "l"(ptr), "r"(r0), "r"(r1), "r"(r2), "r"(r3) : "memory")

__device__ __forceinline__ void mma16816(float c[4], const unsigned a[4], const unsigned b[2]) {
    asm volatile("mma.sync.aligned.m16n8k16.row.col.f32.f16.f16.f32 "
                 "{%0,%1,%2,%3}, {%4,%5,%6,%7}, {%8,%9}, {%0,%1,%2,%3};"
                 : "+f"(c[0]), "+f"(c[1]), "+f"(c[2]), "+f"(c[3])
                 : "r"(a[0]), "r"(a[1]), "r"(a[2]), "r"(a[3]),
                   "r"(b[0]), "r"(b[1]));
}

// ---------------------------------------------------------------------------
// Binning pass 1: per-block etype histogram (4096 edges / block)
// ---------------------------------------------------------------------------
__global__ void __launch_bounds__(256)
bin_hist_kernel(const int* __restrict__ et, int E)
{
    __shared__ int cnt[4];
    if (threadIdx.x < 4) cnt[threadIdx.x] = 0;
    __syncthreads();
    const int base = blockIdx.x * HIST_CHUNK;
#pragma unroll
    for (int i = 0; i < HIST_CHUNK / 256; i++) {
        int e = base + i * 256 + threadIdx.x;
        if (e < E) atomicAdd(&cnt[__ldg(et + e)], 1);
    }
    __syncthreads();
    if (threadIdx.x < 4) g_bh[blockIdx.x * 4 + threadIdx.x] = cnt[threadIdx.x];
}

// ---------------------------------------------------------------------------
// Binning pass 2: single-block scan; 16-aligned bin starts; dummy fill; meta.
// ---------------------------------------------------------------------------
__device__ __forceinline__ int blk_exscan(int v, int* wsum, int tid, int* total) {
    const int lane = tid & 31, wid = tid >> 5;
    int x = v;
#pragma unroll
    for (int o = 1; o < 32; o <<= 1) {
        int y = __shfl_up_sync(0xffffffffu, x, o);
        if (lane >= o) x += y;
    }
    if (lane == 31) wsum[wid] = x;
    __syncthreads();
    if (tid < 32) {
        int s = wsum[tid];
        int t = s;
#pragma unroll
        for (int o = 1; o < 32; o <<= 1) {
            int y = __shfl_up_sync(0xffffffffu, t, o);
            if (tid >= o) t += y;
        }
        wsum[tid] = t - s;
        if (tid == 31) wsum[32] = t;
    }
    __syncthreads();
    int r = x - v + wsum[wid];
    *total = wsum[32];
    __syncthreads();
    return r;
}

__global__ void __launch_bounds__(1024)
bin_scan_kernel(int nb, int N)
{
    __shared__ int wsum[33];
    const int tid = threadIdx.x;
    int ex[4], tot[4];
#pragma unroll
    for (int r = 0; r < 4; r++) {
        int v = (tid < nb) ? g_bh[tid * 4 + r] : 0;
        ex[r] = blk_exscan(v, wsum, tid, &tot[r]);
    }
    int start[5];
    start[0] = 0;
#pragma unroll
    for (int r = 0; r < 4; r++)
        start[r + 1] = (start[r] + tot[r] + 15) & ~15;

    if (tid < nb) {
#pragma unroll
        for (int r = 0; r < 4; r++)
            g_bb[tid * 4 + r] = start[r] + ex[r];
    }
#pragma unroll
    for (int r = 0; r < 4; r++) {
        int gs = start[r] + tot[r];
        int i = gs + tid;
        if (i < start[r + 1]) g_bedge[i] = make_int2(0, N);
    }
    if (tid < 4) g_meta[tid] = start[tid + 1];
}

// ---------------------------------------------------------------------------
// Binning pass 3: scatter with warp-aggregated smem cursor atomics
// ---------------------------------------------------------------------------
__global__ void __launch_bounds__(256)
bin_scatter_kernel(const int* __restrict__ src,
                   const int* __restrict__ dst,
                   const int* __restrict__ et, int E)
{
    __shared__ int cur[4];
    if (threadIdx.x < 4) cur[threadIdx.x] = g_bb[blockIdx.x * 4 + threadIdx.x];
    __syncthreads();
    const int lane = threadIdx.x & 31;
    const int base = blockIdx.x * HIST_CHUNK;
#pragma unroll
    for (int i = 0; i < HIST_CHUNK / 256; i++) {
        int e = base + i * 256 + threadIdx.x;
        bool valid = (e < E);
        int r = valid ? __ldg(et + e) : -1;
        int s = valid ? __ldg(src + e) : 0;
        int d = valid ? __ldg(dst + e) : 0;

        unsigned grp = __match_any_sync(0xffffffffu, r);
        int leader = __ffs(grp) - 1;
        int rank = __popc(grp & ((1u << lane) - 1));
        int pos0 = 0;
        if (lane == leader && r >= 0)
            pos0 = atomicAdd(&cur[r], __popc(grp));
        pos0 = __shfl_sync(grp, pos0, leader);
        if (valid) g_bedge[pos0 + rank] = make_int2(s, d);
    }
}

// ---------------------------------------------------------------------------
// proj1: aggA[n] = x[n]@Wl + bias (layout L), h16[n] = fp16(x[n]) (layout L).
// ---------------------------------------------------------------------------
__global__ void __launch_bounds__(256)
proj1_kernel(const float* __restrict__ x,
             const float* __restrict__ Wl,
             const float* __restrict__ bias,
             __half* __restrict__ h16,
             __half* __restrict__ agg,
             int nTiles)
{
    const int lane   = threadIdx.x & 31;
    const int warpId = (blockIdx.x * blockDim.x + threadIdx.x) >> 5;
    const int nWarps = (gridDim.x * blockDim.x) >> 5;
    const int kq = 2 * (lane & 3);
    const int nq = lane >> 2;
    const int p  = lane & 3;

    unsigned wf[4][2][2];
#pragma unroll
    for (int g = 0; g < 4; g++)
#pragma unroll
        for (int s = 0; s < 2; s++) {
            const int c  = 8 * g + nq;
            const int k0 = 16 * s + kq;
            wf[g][s][0] = pack_h2(__ldg(Wl + k0 * 32 + c),       __ldg(Wl + (k0 + 1) * 32 + c));
            wf[g][s][1] = pack_h2(__ldg(Wl + (k0 + 8) * 32 + c), __ldg(Wl + (k0 + 9) * 32 + c));
        }
    float2 bvec[4];
#pragma unroll
    for (int g = 0; g < 4; g++)
        bvec[g] = make_float2(__ldg(bias + kq + 8 * g), __ldg(bias + kq + 1 + 8 * g));

    for (int t = warpId; t < nTiles; t += nWarps) {
        const int m0 = t * 16;
        const float* r0 = x + (size_t)(m0 + nq) * DD + kq;
        const float* r1 = r0 + 8 * DD;
        float2 x0a = *(const float2*)(r0);
        float2 x0b = *(const float2*)(r0 + 8);
        float2 x0c = *(const float2*)(r0 + 16);
        float2 x0d = *(const float2*)(r0 + 24);
        float2 x1a = *(const float2*)(r1);
        float2 x1b = *(const float2*)(r1 + 8);
        float2 x1c = *(const float2*)(r1 + 16);
        float2 x1d = *(const float2*)(r1 + 24);

        unsigned A0[4] = { pack_h2(x0a.x, x0a.y), pack_h2(x1a.x, x1a.y),
                           pack_h2(x0b.x, x0b.y), pack_h2(x1b.x, x1b.y) };
        unsigned A1[4] = { pack_h2(x0c.x, x0c.y), pack_h2(x1c.x, x1c.y),
                           pack_h2(x0d.x, x0d.y), pack_h2(x1d.x, x1d.y) };

        float acc[4][4];
#pragma unroll
        for (int g = 0; g < 4; g++) {
            acc[g][0] = 0.f; acc[g][1] = 0.f; acc[g][2] = 0.f; acc[g][3] = 0.f;
        }
#pragma unroll
        for (int g = 0; g < 4; g++) {
            mma16816(acc[g], A0, wf[g][0]);
            mma16816(acc[g], A1, wf[g][1]);
        }

        *reinterpret_cast<uint4*>(h16 + (size_t)(m0 + nq) * DD + 8 * p) =
            make_uint4(A0[0], A0[2], A1[0], A1[2]);
        *reinterpret_cast<uint4*>(h16 + (size_t)(m0 + nq + 8) * DD + 8 * p) =
            make_uint4(A0[1], A0[3], A1[1], A1[3]);

        *reinterpret_cast<uint4*>(agg + (size_t)(m0 + nq) * DD + 8 * p) =
            make_uint4(pack_h2(acc[0][0] + bvec[0].x, acc[0][1] + bvec[0].y),
                       pack_h2(acc[1][0] + bvec[1].x, acc[1][1] + bvec[1].y),
                       pack_h2(acc[2][0] + bvec[2].x, acc[2][1] + bvec[2].y),
                       pack_h2(acc[3][0] + bvec[3].x, acc[3][1] + bvec[3].y));
        *reinterpret_cast<uint4*>(agg + (size_t)(m0 + nq + 8) * DD + 8 * p) =
            make_uint4(pack_h2(acc[0][2] + bvec[0].x, acc[0][3] + bvec[0].y),
                       pack_h2(acc[1][2] + bvec[1].x, acc[1][3] + bvec[1].y),
                       pack_h2(acc[2][2] + bvec[2].x, acc[2][3] + bvec[2].y),
                       pack_h2(acc[3][2] + bvec[3].x, acc[3][3] + bvec[3].y));
    }
}

// ---------------------------------------------------------------------------
// edge_mma (layer 1, RELU=false): block quarter -> relation; depth-2 row
// pipeline with idx prefetched one extra iteration ahead.
// ---------------------------------------------------------------------------
__global__ void __launch_bounds__(256, 3)
edge_mma_kernel(const __half* __restrict__ h,
                const float* __restrict__ W,
                __half* __restrict__ agg)
{
    const int lane = threadIdx.x & 31;
    const int kq = 2 * (lane & 3);
    const int nq = lane >> 2;
    const int p  = lane & 3;

    const int blocksPerRel = gridDim.x >> 2;
    const int r = blockIdx.x / blocksPerRel;
    const int warpInQ = (blockIdx.x % blocksPerRel) * (blockDim.x >> 5) + (threadIdx.x >> 5);
    const int q = blocksPerRel * (blockDim.x >> 5);

    unsigned bf[4][2][2];
    {
        const float* Wr = W + r * 1024;
#pragma unroll
        for (int g = 0; g < 4; g++)
#pragma unroll
            for (int s = 0; s < 2; s++) {
                const int c  = 8 * g + nq;
                const int k0 = 16 * s + kq;
                bf[g][s][0] = pack_h2(__ldg(Wr + k0 * 32 + c),       __ldg(Wr + (k0 + 1) * 32 + c));
                bf[g][s][1] = pack_h2(__ldg(Wr + (k0 + 8) * 32 + c), __ldg(Wr + (k0 + 9) * 32 + c));
            }
    }

    const int tBeg = (r == 0) ? 0 : (g_meta[r - 1] >> 4);
    const int tEnd = g_meta[r] >> 4;

    int t = tBeg + warpInQ;
    if (t >= tEnd) return;

    int dv0 = 0, sv1 = 0, dv1 = 0;
    uint4 uA0, uB0;
    {
        int sv = 0;
        if (lane < 16) {
            int2 ed = __ldg(&g_bedge[t * 16 + lane]);
            sv = ed.x; dv0 = ed.y;
        }
        int sA = __shfl_sync(0xffffffffu, sv, nq);
        int sB = __shfl_sync(0xffffffffu, sv, nq + 8);
        uA0 = *reinterpret_cast<const uint4*>(h + (size_t)sA * DD + 8 * p);
        uB0 = *reinterpret_cast<const uint4*>(h + (size_t)sB * DD + 8 * p);
    }
    int t1 = t + q;
    if (t1 < tEnd && lane < 16) {
        int2 ed = __ldg(&g_bedge[t1 * 16 + lane]);
        sv1 = ed.x; dv1 = ed.y;
    }

    for (;;) {
        uint4 uA1, uB1;
        if (t1 < tEnd) {
            int sA = __shfl_sync(0xffffffffu, sv1, nq);
            int sB = __shfl_sync(0xffffffffu, sv1, nq + 8);
            uA1 = *reinterpret_cast<const uint4*>(h + (size_t)sA * DD + 8 * p);
            uB1 = *reinterpret_cast<const uint4*>(h + (size_t)sB * DD + 8 * p);
        }
        const int t2 = t1 + q;
        int sv2 = 0, dv2 = 0;
        if (t2 < tEnd && lane < 16) {
            int2 ed = __ldg(&g_bedge[t2 * 16 + lane]);
            sv2 = ed.x; dv2 = ed.y;
        }

        unsigned A0[4] = { uA0.x, uB0.x, uA0.y, uB0.y };
        unsigned A1[4] = { uA0.z, uB0.z, uA0.w, uB0.w };

        float acc[4][4];
#pragma unroll
        for (int g = 0; g < 4; g++) {
            acc[g][0] = 0.f; acc[g][1] = 0.f; acc[g][2] = 0.f; acc[g][3] = 0.f;
        }
#pragma unroll
        for (int g = 0; g < 4; g++) {
            mma16816(acc[g], A0, bf[g][0]);
            mma16816(acc[g], A1, bf[g][1]);
        }

        const int dA = __shfl_sync(0xffffffffu, dv0, nq);
        const int dB = __shfl_sync(0xffffffffu, dv0, nq + 8);

        __half* pA = agg + (size_t)dA * DD + 8 * p;
        RED16(pA, pack_h2(acc[0][0], acc[0][1]), pack_h2(acc[1][0], acc[1][1]),
                  pack_h2(acc[2][0], acc[2][1]), pack_h2(acc[3][0], acc[3][1]));
        __half* pB = agg + (size_t)dB * DD + 8 * p;
        RED16(pB, pack_h2(acc[0][2], acc[0][3]), pack_h2(acc[1][2], acc[1][3]),
                  pack_h2(acc[2][2], acc[2][3]), pack_h2(acc[3][2], acc[3][3]));

        if (t1 >= tEnd) break;
        t = t1; t1 = t2;
        dv0 = dv1; sv1 = sv2; dv1 = dv2;
        uA0 = uA1; uB0 = uB1;
    }
}

// ---------------------------------------------------------------------------
// layer2 fused: grid interleaves edge blocks (8/9) and proj blocks (1/9).
// Both RED into pre-zeroed aggB; relu applied to all aggA reads.
//   edge blocks: aggB[dst] += relu(aggA[src]) @ W_etype
//   proj blocks: aggB[n]   += relu(aggA[n]) @ Wl + bias
// ---------------------------------------------------------------------------
__global__ void __launch_bounds__(256, 3)
layer2_fused_kernel(const __half* __restrict__ h,      // aggA
                    const float* __restrict__ W,
                    const float* __restrict__ Wl,
                    const float* __restrict__ bias,
                    __half* __restrict__ agg,          // aggB (zeroed)
                    int nTilesN)
{
    const int lane = threadIdx.x & 31;
    const int kq = 2 * (lane & 3);
    const int nq = lane >> 2;
    const int p  = lane & 3;

    const bool projRole = (blockIdx.x % 9) == 8;

    if (projRole) {
        // ---------------- proj role ----------------
        const int projBlk  = blockIdx.x / 9;
        const int nProjBlk = gridDim.x / 9;
        const int warpId = projBlk * (blockDim.x >> 5) + (threadIdx.x >> 5);
        const int nWarps = nProjBlk * (blockDim.x >> 5);

        unsigned wf[4][2][2];
#pragma unroll
        for (int g = 0; g < 4; g++)
#pragma unroll
            for (int s = 0; s < 2; s++) {
                const int c  = 8 * g + nq;
                const int k0 = 16 * s + kq;
                wf[g][s][0] = pack_h2(__ldg(Wl + k0 * 32 + c),       __ldg(Wl + (k0 + 1) * 32 + c));
                wf[g][s][1] = pack_h2(__ldg(Wl + (k0 + 8) * 32 + c), __ldg(Wl + (k0 + 9) * 32 + c));
            }
        float2 bvec[4];
#pragma unroll
        for (int g = 0; g < 4; g++)
            bvec[g] = make_float2(__ldg(bias + kq + 8 * g), __ldg(bias + kq + 1 + 8 * g));

        for (int t = warpId; t < nTilesN; t += nWarps) {
            const int m0 = t * 16;
            uint4 uA = *reinterpret_cast<const uint4*>(h + (size_t)(m0 + nq) * DD + 8 * p);
            uint4 uB = *reinterpret_cast<const uint4*>(h + (size_t)(m0 + nq + 8) * DD + 8 * p);

            unsigned A0[4] = { relu_u(uA.x), relu_u(uB.x), relu_u(uA.y), relu_u(uB.y) };
            unsigned A1[4] = { relu_u(uA.z), relu_u(uB.z), relu_u(uA.w), relu_u(uB.w) };

            float acc[4][4];
#pragma unroll
            for (int g = 0; g < 4; g++) {
                acc[g][0] = 0.f; acc[g][1] = 0.f; acc[g][2] = 0.f; acc[g][3] = 0.f;
            }
#pragma unroll
            for (int g = 0; g < 4; g++) {
                mma16816(acc[g], A0, wf[g][0]);
                mma16816(acc[g], A1, wf[g][1]);
            }

            __half* agA = agg + (size_t)(m0 + nq) * DD + 8 * p;
            RED16(agA,
                  pack_h2(acc[0][0] + bvec[0].x, acc[0][1] + bvec[0].y),
                  pack_h2(acc[1][0] + bvec[1].x, acc[1][1] + bvec[1].y),
                  pack_h2(acc[2][0] + bvec[2].x, acc[2][1] + bvec[2].y),
                  pack_h2(acc[3][0] + bvec[3].x, acc[3][1] + bvec[3].y));
            __half* agB = agg + (size_t)(m0 + nq + 8) * DD + 8 * p;
            RED16(agB,
                  pack_h2(acc[0][2] + bvec[0].x, acc[0][3] + bvec[0].y),
                  pack_h2(acc[1][2] + bvec[1].x, acc[1][3] + bvec[1].y),
                  pack_h2(acc[2][2] + bvec[2].x, acc[2][3] + bvec[2].y),
                  pack_h2(acc[3][2] + bvec[3].x, acc[3][3] + bvec[3].y));
        }
        return;
    }

    // ---------------- edge role ----------------
    const int ebid = blockIdx.x - blockIdx.x / 9;      // 0..(8/9*grid - 1)
    const int nEdgeBlk = gridDim.x - gridDim.x / 9;
    const int blocksPerRel = nEdgeBlk >> 2;
    const int r = ebid / blocksPerRel;
    const int warpInQ = (ebid % blocksPerRel) * (blockDim.x >> 5) + (threadIdx.x >> 5);
    const int q = blocksPerRel * (blockDim.x >> 5);

    unsigned bf[4][2][2];
    {
        const float* Wr = W + r * 1024;
#pragma unroll
        for (int g = 0; g < 4; g++)
#pragma unroll
            for (int s = 0; s < 2; s++) {
                const int c  = 8 * g + nq;
                const int k0 = 16 * s + kq;
                bf[g][s][0] = pack_h2(__ldg(Wr + k0 * 32 + c),       __ldg(Wr + (k0 + 1) * 32 + c));
                bf[g][s][1] = pack_h2(__ldg(Wr + (k0 + 8) * 32 + c), __ldg(Wr + (k0 + 9) * 32 + c));
            }
    }

    const int tBeg = (r == 0) ? 0 : (g_meta[r - 1] >> 4);
    const int tEnd = g_meta[r] >> 4;

    int t = tBeg + warpInQ;
    if (t >= tEnd) return;

    int dv0 = 0, sv1 = 0, dv1 = 0;
    uint4 uA0, uB0;
    {
        int sv = 0;
        if (lane < 16) {
            int2 ed = __ldg(&g_bedge[t * 16 + lane]);
            sv = ed.x; dv0 = ed.y;
        }
        int sA = __shfl_sync(0xffffffffu, sv, nq);
        int sB = __shfl_sync(0xffffffffu, sv, nq + 8);
        uA0 = *reinterpret_cast<const uint4*>(h + (size_t)sA * DD + 8 * p);
        uB0 = *reinterpret_cast<const uint4*>(h + (size_t)sB * DD + 8 * p);
    }
    int t1 = t + q;
    if (t1 < tEnd && lane < 16) {
        int2 ed = __ldg(&g_bedge[t1 * 16 + lane]);
        sv1 = ed.x; dv1 = ed.y;
    }

    for (;;) {
        uint4 uA1, uB1;
        if (t1 < tEnd) {
            int sA = __shfl_sync(0xffffffffu, sv1, nq);
            int sB = __shfl_sync(0xffffffffu, sv1, nq + 8);
            uA1 = *reinterpret_cast<const uint4*>(h + (size_t)sA * DD + 8 * p);
            uB1 = *reinterpret_cast<const uint4*>(h + (size_t)sB * DD + 8 * p);
        }
        const int t2 = t1 + q;
        int sv2 = 0, dv2 = 0;
        if (t2 < tEnd && lane < 16) {
            int2 ed = __ldg(&g_bedge[t2 * 16 + lane]);
            sv2 = ed.x; dv2 = ed.y;
        }

        unsigned A0[4] = { relu_u(uA0.x), relu_u(uB0.x), relu_u(uA0.y), relu_u(uB0.y) };
        unsigned A1[4] = { relu_u(uA0.z), relu_u(uB0.z), relu_u(uA0.w), relu_u(uB0.w) };

        float acc[4][4];
#pragma unroll
        for (int g = 0; g < 4; g++) {
            acc[g][0] = 0.f; acc[g][1] = 0.f; acc[g][2] = 0.f; acc[g][3] = 0.f;
        }
#pragma unroll
        for (int g = 0; g < 4; g++) {
            mma16816(acc[g], A0, bf[g][0]);
            mma16816(acc[g], A1, bf[g][1]);
        }

        const int dA = __shfl_sync(0xffffffffu, dv0, nq);
        const int dB = __shfl_sync(0xffffffffu, dv0, nq + 8);

        __half* pA = agg + (size_t)dA * DD + 8 * p;
        RED16(pA, pack_h2(acc[0][0], acc[0][1]), pack_h2(acc[1][0], acc[1][1]),
                  pack_h2(acc[2][0], acc[2][1]), pack_h2(acc[3][0], acc[3][1]));
        __half* pB = agg + (size_t)dB * DD + 8 * p;
        RED16(pB, pack_h2(acc[0][2], acc[0][3]), pack_h2(acc[1][2], acc[1][3]),
                  pack_h2(acc[2][2], acc[2][3]), pack_h2(acc[3][2], acc[3][3]));

        if (t1 >= tEnd) break;
        t = t1; t1 = t2;
        dv0 = dv1; sv1 = sv2; dv1 = dv2;
        uA0 = uA1; uB0 = uB1;
    }
}

// ---------------------------------------------------------------------------
// mean: out[m][f(j)] = mean_a relu(agg[m*32+a][j])  (agg in layout L)
// ---------------------------------------------------------------------------
__global__ void mean_kernel(const __half* __restrict__ agg,
                            float* __restrict__ out, int M)
{
    int j = threadIdx.x & 31;
    int m = (blockIdx.x * blockDim.x + threadIdx.x) >> 5;
    if (m >= M) return;
    float s = 0.0f;
#pragma unroll
    for (int a = 0; a < 32; a++)
        s += fmaxf(__half2float(agg[((size_t)m * 32 + a) * DD + j]), 0.0f);
    const int f = 2 * (j >> 3) + 8 * ((j & 7) >> 1) + (j & 1);
    out[(size_t)m * DD + f] = s * (1.0f / 32.0f);
}

// ---------------------------------------------------------------------------
extern "C" void kernel_launch(void* const* d_in, const int* in_sizes, int n_in,
                              void* d_out, int out_size)
{
    const float* x    = (const float*)d_in[0];
    const float* W    = (const float*)d_in[1];
    const float* Wl   = (const float*)d_in[2];
    const float* bias = (const float*)d_in[3];
    const int*   src  = (const int*)d_in[4];
    const int*   dst  = (const int*)d_in[5];
    const int*   et   = (const int*)d_in[6];
    float* out = (float*)d_out;

    const int N = in_sizes[0] / DD;
    const int E = in_sizes[4];
    const int M = out_size / DD;
    const int nTilesN = N / 16;
    const int nb = (E + HIST_CHUNK - 1) / HIST_CHUNK;

    void *hP = nullptr, *aP = nullptr, *bP = nullptr;
    cudaGetSymbolAddress(&hP, g_h16);
    cudaGetSymbolAddress(&aP, g_aggA);
    cudaGetSymbolAddress(&bP, g_aggB);
    __half* h16  = (__half*)hP;
    __half* aggA = (__half*)aP;
    __half* aggB = (__half*)bP;
    const size_t aggBytes = (size_t)(N + 16) * DD * sizeof(__half);

    // Side stream + events: created once on the uncaptured correctness call,
    // then reused inside graph capture (fork/join pattern).
    static cudaStream_t sB = nullptr;
    static cudaEvent_t eFork, eP1;
    if (!sB) {
        cudaStreamCreateWithFlags(&sB, cudaStreamNonBlocking);
        cudaEventCreateWithFlags(&eFork, cudaEventDisableTiming);
        cudaEventCreateWithFlags(&eP1,   cudaEventDisableTiming);
    }

    const int projBlocks  = 1024;
    const int edgeBlocks  = 8192;            // layer-1 edge: 4 quarters x 2048
    const int fusedBlocks = 9216;            // layer-2: 8192 edge + 1024 proj (every 9th)
    const int meanBlocks  = (M * 32 + 255) / 256;

    // ---- Fork: proj1 on side stream; binning + aggB memset on default ----
    cudaEventRecord(eFork, 0);
    cudaStreamWaitEvent(sB, eFork, 0);
    proj1_kernel<<<projBlocks, 256, 0, sB>>>(x, Wl, bias, h16, aggA, nTilesN);
    cudaEventRecord(eP1, sB);

    bin_hist_kernel<<<nb, 256>>>(et, E);
    bin_scan_kernel<<<1, 1024>>>(nb, N);
    bin_scatter_kernel<<<nb, 256>>>(src, dst, et, E);
    cudaMemsetAsync(bP, 0, aggBytes, 0);     // aggB zero for layer-2 REDs

    // ---- Join, then Layer 1 edge ----
    cudaStreamWaitEvent(0, eP1, 0);
    edge_mma_kernel<<<edgeBlocks, 256>>>(h16, W, aggA);

    // ---- Layer 2: fused edge + self-loop proj (both RED into aggB) ----
    layer2_fused_kernel<<<fusedBlocks, 256>>>(aggA, W, Wl, bias, aggB, nTilesN);

    // ---- Per-molecule mean (relu fused) ----
    mean_kernel<<<meanBlocks, 256>>>(aggB, out, M);
}

// round 17
// speedup vs baseline: 1.0958x; 1.0958x over previous
#include <cuda_runtime.h>
#include <cuda_fp16.h>
#include <cstdint>

#define NMAX 1048576
#define EMAX 4194304
#define DD   32
#define RR   4
#define HIST_CHUNK 4096
#define MAXBLK (EMAX / HIST_CHUNK)   // 1024

// Node feature arrays use "layout L": within a 32-half row, position
// j = 8q + 2m + odd holds feature f = 2q + 8m + odd  (q,m in 0..3).
__device__ __half g_h16[(size_t)NMAX * DD];          // 64 MB layer-1 input (layout L)
__device__ __half g_aggA[(size_t)(NMAX + 16) * DD];  // 64 MB (+dummy rows, layout L)
__device__ __half g_aggB[(size_t)(NMAX + 16) * DD];  // 64 MB (+dummy rows, layout L)
__device__ int2   g_bedge[EMAX + 64];                // edges binned by etype: (src, dst)
__device__ int    g_bh[MAXBLK * RR];
__device__ int    g_bb[MAXBLK * RR];
__device__ int    g_meta[4];                         // bin ends (16-aligned)

// ---------------------------------------------------------------------------
__device__ __forceinline__ unsigned pack_h2(float a, float b) {
    __half2 h = __floats2half2_rn(a, b);
    return *reinterpret_cast<unsigned*>(&h);
}
__device__ __forceinline__ unsigned relu_u(unsigned v) {
    __half2 h = *reinterpret_cast<__half2*>(&v);
    h = __hmax2(h, __float2half2_rn(0.0f));
    return *reinterpret_cast<unsigned*>(&h);
}
#define RED16(ptr, r0, r1, r2, r3)                                             \
    asm volatile("red.global.add.noftz.v4.f16x2 [%0], {%1, %2, %3, %4};"      \
                 :: "l"(ptr), "r"(r0), "r"(r1), "r"(r2), "r"(r3) : "memory")

// L2 cache policies (created once per thread; cheap)
__device__ __forceinline__ unsigned long long mkpol_evict_last() {
    unsigned long long pol;
    asm("createpolicy.fractional.L2::evict_last.b64 %0, 1.0;" : "=l"(pol));
    return pol;
}
__device__ __forceinline__ unsigned long long mkpol_evict_first() {
    unsigned long long pol;
    asm("createpolicy.fractional.L2::evict_first.b64 %0, 1.0;" : "=l"(pol));
    return pol;
}
// h-row gather with evict_last policy (pin h in L2 against the RED stream)
__device__ __forceinline__ uint4 ldg_row_el(const __half* p, unsigned long long pol) {
    uint4 v;
    asm volatile("ld.global.nc.L2::cache_hint.v4.u32 {%0,%1,%2,%3}, [%4], %5;"
                 : "=r"(v.x), "=r"(v.y), "=r"(v.z), "=r"(v.w)
                 : "l"(p), "l"(pol));
    return v;
}
// streamed index load with evict_first policy (read-once)
__device__ __forceinline__ int2 ldg_idx_ef(const int2* p, unsigned long long pol) {
    int2 v;
    asm volatile("ld.global.nc.L2::cache_hint.v2.u32 {%0,%1}, [%2], %3;"
                 : "=r"(v.x), "=r"(v.y)
                 : "l"(p), "l"(pol));
    return v;
}

__device__ __forceinline__ void mma16816(float c[4], const unsigned a[4], const unsigned b[2]) {
    asm volatile("mma.sync.aligned.m16n8k16.row.col.f32.f16.f16.f32 "
                 "{%0,%1,%2,%3}, {%4,%5,%6,%7}, {%8,%9}, {%0,%1,%2,%3};"
                 : "+f"(c[0]), "+f"(c[1]), "+f"(c[2]), "+f"(c[3])
                 : "r"(a[0]), "r"(a[1]), "r"(a[2]), "r"(a[3]),
                   "r"(b[0]), "r"(b[1]));
}

// ---------------------------------------------------------------------------
// Binning pass 1: per-block etype histogram (4096 edges / block)
// ---------------------------------------------------------------------------
__global__ void __launch_bounds__(256)
bin_hist_kernel(const int* __restrict__ et, int E)
{
    __shared__ int cnt[4];
    if (threadIdx.x < 4) cnt[threadIdx.x] = 0;
    __syncthreads();
    const int base = blockIdx.x * HIST_CHUNK;
#pragma unroll
    for (int i = 0; i < HIST_CHUNK / 256; i++) {
        int e = base + i * 256 + threadIdx.x;
        if (e < E) atomicAdd(&cnt[__ldg(et + e)], 1);
    }
    __syncthreads();
    if (threadIdx.x < 4) g_bh[blockIdx.x * 4 + threadIdx.x] = cnt[threadIdx.x];
}

// ---------------------------------------------------------------------------
// Binning pass 2: single-block scan; 16-aligned bin starts; dummy fill; meta.
// ---------------------------------------------------------------------------
__device__ __forceinline__ int blk_exscan(int v, int* wsum, int tid, int* total) {
    const int lane = tid & 31, wid = tid >> 5;
    int x = v;
#pragma unroll
    for (int o = 1; o < 32; o <<= 1) {
        int y = __shfl_up_sync(0xffffffffu, x, o);
        if (lane >= o) x += y;
    }
    if (lane == 31) wsum[wid] = x;
    __syncthreads();
    if (tid < 32) {
        int s = wsum[tid];
        int t = s;
#pragma unroll
        for (int o = 1; o < 32; o <<= 1) {
            int y = __shfl_up_sync(0xffffffffu, t, o);
            if (tid >= o) t += y;
        }
        wsum[tid] = t - s;
        if (tid == 31) wsum[32] = t;
    }
    __syncthreads();
    int r = x - v + wsum[wid];
    *total = wsum[32];
    __syncthreads();
    return r;
}

__global__ void __launch_bounds__(1024)
bin_scan_kernel(int nb, int N)
{
    __shared__ int wsum[33];
    const int tid = threadIdx.x;
    int ex[4], tot[4];
#pragma unroll
    for (int r = 0; r < 4; r++) {
        int v = (tid < nb) ? g_bh[tid * 4 + r] : 0;
        ex[r] = blk_exscan(v, wsum, tid, &tot[r]);
    }
    int start[5];
    start[0] = 0;
#pragma unroll
    for (int r = 0; r < 4; r++)
        start[r + 1] = (start[r] + tot[r] + 15) & ~15;

    if (tid < nb) {
#pragma unroll
        for (int r = 0; r < 4; r++)
            g_bb[tid * 4 + r] = start[r] + ex[r];
    }
#pragma unroll
    for (int r = 0; r < 4; r++) {
        int gs = start[r] + tot[r];
        int i = gs + tid;
        if (i < start[r + 1]) g_bedge[i] = make_int2(0, N);
    }
    if (tid < 4) g_meta[tid] = start[tid + 1];
}

// ---------------------------------------------------------------------------
// Binning pass 3: scatter with warp-aggregated smem cursor atomics
// ---------------------------------------------------------------------------
__global__ void __launch_bounds__(256)
bin_scatter_kernel(const int* __restrict__ src,
                   const int* __restrict__ dst,
                   const int* __restrict__ et, int E)
{
    __shared__ int cur[4];
    if (threadIdx.x < 4) cur[threadIdx.x] = g_bb[blockIdx.x * 4 + threadIdx.x];
    __syncthreads();
    const int lane = threadIdx.x & 31;
    const int base = blockIdx.x * HIST_CHUNK;
#pragma unroll
    for (int i = 0; i < HIST_CHUNK / 256; i++) {
        int e = base + i * 256 + threadIdx.x;
        bool valid = (e < E);
        int r = valid ? __ldg(et + e) : -1;
        int s = valid ? __ldg(src + e) : 0;
        int d = valid ? __ldg(dst + e) : 0;

        unsigned grp = __match_any_sync(0xffffffffu, r);
        int leader = __ffs(grp) - 1;
        int rank = __popc(grp & ((1u << lane) - 1));
        int pos0 = 0;
        if (lane == leader && r >= 0)
            pos0 = atomicAdd(&cur[r], __popc(grp));
        pos0 = __shfl_sync(grp, pos0, leader);
        if (valid) g_bedge[pos0 + rank] = make_int2(s, d);
    }
}

// ---------------------------------------------------------------------------
// proj1: aggA[n] = x[n]@Wl + bias (layout L), h16[n] = fp16(x[n]) (layout L).
// ---------------------------------------------------------------------------
__global__ void __launch_bounds__(256)
proj1_kernel(const float* __restrict__ x,
             const float* __restrict__ Wl,
             const float* __restrict__ bias,
             __half* __restrict__ h16,
             __half* __restrict__ agg,
             int nTiles)
{
    const int lane   = threadIdx.x & 31;
    const int warpId = (blockIdx.x * blockDim.x + threadIdx.x) >> 5;
    const int nWarps = (gridDim.x * blockDim.x) >> 5;
    const int kq = 2 * (lane & 3);
    const int nq = lane >> 2;
    const int p  = lane & 3;

    unsigned wf[4][2][2];
#pragma unroll
    for (int g = 0; g < 4; g++)
#pragma unroll
        for (int s = 0; s < 2; s++) {
            const int c  = 8 * g + nq;
            const int k0 = 16 * s + kq;
            wf[g][s][0] = pack_h2(__ldg(Wl + k0 * 32 + c),       __ldg(Wl + (k0 + 1) * 32 + c));
            wf[g][s][1] = pack_h2(__ldg(Wl + (k0 + 8) * 32 + c), __ldg(Wl + (k0 + 9) * 32 + c));
        }
    float2 bvec[4];
#pragma unroll
    for (int g = 0; g < 4; g++)
        bvec[g] = make_float2(__ldg(bias + kq + 8 * g), __ldg(bias + kq + 1 + 8 * g));

    for (int t = warpId; t < nTiles; t += nWarps) {
        const int m0 = t * 16;
        const float* r0 = x + (size_t)(m0 + nq) * DD + kq;
        const float* r1 = r0 + 8 * DD;
        float2 x0a = *(const float2*)(r0);
        float2 x0b = *(const float2*)(r0 + 8);
        float2 x0c = *(const float2*)(r0 + 16);
        float2 x0d = *(const float2*)(r0 + 24);
        float2 x1a = *(const float2*)(r1);
        float2 x1b = *(const float2*)(r1 + 8);
        float2 x1c = *(const float2*)(r1 + 16);
        float2 x1d = *(const float2*)(r1 + 24);

        unsigned A0[4] = { pack_h2(x0a.x, x0a.y), pack_h2(x1a.x, x1a.y),
                           pack_h2(x0b.x, x0b.y), pack_h2(x1b.x, x1b.y) };
        unsigned A1[4] = { pack_h2(x0c.x, x0c.y), pack_h2(x1c.x, x1c.y),
                           pack_h2(x0d.x, x0d.y), pack_h2(x1d.x, x1d.y) };

        float acc[4][4];
#pragma unroll
        for (int g = 0; g < 4; g++) {
            acc[g][0] = 0.f; acc[g][1] = 0.f; acc[g][2] = 0.f; acc[g][3] = 0.f;
        }
#pragma unroll
        for (int g = 0; g < 4; g++) {
            mma16816(acc[g], A0, wf[g][0]);
            mma16816(acc[g], A1, wf[g][1]);
        }

        *reinterpret_cast<uint4*>(h16 + (size_t)(m0 + nq) * DD + 8 * p) =
            make_uint4(A0[0], A0[2], A1[0], A1[2]);
        *reinterpret_cast<uint4*>(h16 + (size_t)(m0 + nq + 8) * DD + 8 * p) =
            make_uint4(A0[1], A0[3], A1[1], A1[3]);

        *reinterpret_cast<uint4*>(agg + (size_t)(m0 + nq) * DD + 8 * p) =
            make_uint4(pack_h2(acc[0][0] + bvec[0].x, acc[0][1] + bvec[0].y),
                       pack_h2(acc[1][0] + bvec[1].x, acc[1][1] + bvec[1].y),
                       pack_h2(acc[2][0] + bvec[2].x, acc[2][1] + bvec[2].y),
                       pack_h2(acc[3][0] + bvec[3].x, acc[3][1] + bvec[3].y));
        *reinterpret_cast<uint4*>(agg + (size_t)(m0 + nq + 8) * DD + 8 * p) =
            make_uint4(pack_h2(acc[0][2] + bvec[0].x, acc[0][3] + bvec[0].y),
                       pack_h2(acc[1][2] + bvec[1].x, acc[1][3] + bvec[1].y),
                       pack_h2(acc[2][2] + bvec[2].x, acc[2][3] + bvec[2].y),
                       pack_h2(acc[3][2] + bvec[3].x, acc[3][3] + bvec[3].y));
    }
}

// ---------------------------------------------------------------------------
// proj2: aggB[n] = relu(aggA[n])@Wl + bias (both layout L).
// ---------------------------------------------------------------------------
__global__ void __launch_bounds__(256)
proj2_kernel(const __half* __restrict__ hin,
             const float* __restrict__ Wl,
             const float* __restrict__ bias,
             __half* __restrict__ agg,
             int nTiles)
{
    const int lane   = threadIdx.x & 31;
    const int warpId = (blockIdx.x * blockDim.x + threadIdx.x) >> 5;
    const int nWarps = (gridDim.x * blockDim.x) >> 5;
    const int kq = 2 * (lane & 3);
    const int nq = lane >> 2;
    const int p  = lane & 3;

    unsigned wf[4][2][2];
#pragma unroll
    for (int g = 0; g < 4; g++)
#pragma unroll
        for (int s = 0; s < 2; s++) {
            const int c  = 8 * g + nq;
            const int k0 = 16 * s + kq;
            wf[g][s][0] = pack_h2(__ldg(Wl + k0 * 32 + c),       __ldg(Wl + (k0 + 1) * 32 + c));
            wf[g][s][1] = pack_h2(__ldg(Wl + (k0 + 8) * 32 + c), __ldg(Wl + (k0 + 9) * 32 + c));
        }
    float2 bvec[4];
#pragma unroll
    for (int g = 0; g < 4; g++)
        bvec[g] = make_float2(__ldg(bias + kq + 8 * g), __ldg(bias + kq + 1 + 8 * g));

    for (int t = warpId; t < nTiles; t += nWarps) {
        const int m0 = t * 16;
        uint4 uA = *reinterpret_cast<const uint4*>(hin + (size_t)(m0 + nq) * DD + 8 * p);
        uint4 uB = *reinterpret_cast<const uint4*>(hin + (size_t)(m0 + nq + 8) * DD + 8 * p);

        unsigned A0[4] = { relu_u(uA.x), relu_u(uB.x), relu_u(uA.y), relu_u(uB.y) };
        unsigned A1[4] = { relu_u(uA.z), relu_u(uB.z), relu_u(uA.w), relu_u(uB.w) };

        float acc[4][4];
#pragma unroll
        for (int g = 0; g < 4; g++) {
            acc[g][0] = 0.f; acc[g][1] = 0.f; acc[g][2] = 0.f; acc[g][3] = 0.f;
        }
#pragma unroll
        for (int g = 0; g < 4; g++) {
            mma16816(acc[g], A0, wf[g][0]);
            mma16816(acc[g], A1, wf[g][1]);
        }

        *reinterpret_cast<uint4*>(agg + (size_t)(m0 + nq) * DD + 8 * p) =
            make_uint4(pack_h2(acc[0][0] + bvec[0].x, acc[0][1] + bvec[0].y),
                       pack_h2(acc[1][0] + bvec[1].x, acc[1][1] + bvec[1].y),
                       pack_h2(acc[2][0] + bvec[2].x, acc[2][1] + bvec[2].y),
                       pack_h2(acc[3][0] + bvec[3].x, acc[3][1] + bvec[3].y));
        *reinterpret_cast<uint4*>(agg + (size_t)(m0 + nq + 8) * DD + 8 * p) =
            make_uint4(pack_h2(acc[0][2] + bvec[0].x, acc[0][3] + bvec[0].y),
                       pack_h2(acc[1][2] + bvec[1].x, acc[1][3] + bvec[1].y),
                       pack_h2(acc[2][2] + bvec[2].x, acc[2][3] + bvec[2].y),
                       pack_h2(acc[3][2] + bvec[3].x, acc[3][3] + bvec[3].y));
    }
}

// ---------------------------------------------------------------------------
// edge_mma: block quarter -> relation; depth-2 row pipeline with idx
// prefetched one extra iteration ahead; evict_last policy on h-row gathers,
// evict_first on the streamed edge list.
// ---------------------------------------------------------------------------
template <bool RELU>
__global__ void __launch_bounds__(256, 3)
edge_mma_kernel(const __half* __restrict__ h,
                const float* __restrict__ W,
                __half* __restrict__ agg)
{
    const int lane = threadIdx.x & 31;
    const int kq = 2 * (lane & 3);
    const int nq = lane >> 2;
    const int p  = lane & 3;

    const unsigned long long polL = mkpol_evict_last();
    const unsigned long long polF = mkpol_evict_first();

    const int blocksPerRel = gridDim.x >> 2;
    const int r = blockIdx.x / blocksPerRel;
    const int warpInQ = (blockIdx.x % blocksPerRel) * (blockDim.x >> 5) + (threadIdx.x >> 5);
    const int q = blocksPerRel * (blockDim.x >> 5);

    unsigned bf[4][2][2];
    {
        const float* Wr = W + r * 1024;
#pragma unroll
        for (int g = 0; g < 4; g++)
#pragma unroll
            for (int s = 0; s < 2; s++) {
                const int c  = 8 * g + nq;
                const int k0 = 16 * s + kq;
                bf[g][s][0] = pack_h2(__ldg(Wr + k0 * 32 + c),       __ldg(Wr + (k0 + 1) * 32 + c));
                bf[g][s][1] = pack_h2(__ldg(Wr + (k0 + 8) * 32 + c), __ldg(Wr + (k0 + 9) * 32 + c));
            }
    }

    const int tBeg = (r == 0) ? 0 : (g_meta[r - 1] >> 4);
    const int tEnd = g_meta[r] >> 4;

    int t = tBeg + warpInQ;
    if (t >= tEnd) return;

    int dv0 = 0, sv1 = 0, dv1 = 0;
    uint4 uA0, uB0;
    {
        int sv = 0;
        if (lane < 16) {
            int2 ed = ldg_idx_ef(&g_bedge[t * 16 + lane], polF);
            sv = ed.x; dv0 = ed.y;
        }
        int sA = __shfl_sync(0xffffffffu, sv, nq);
        int sB = __shfl_sync(0xffffffffu, sv, nq + 8);
        uA0 = ldg_row_el(h + (size_t)sA * DD + 8 * p, polL);
        uB0 = ldg_row_el(h + (size_t)sB * DD + 8 * p, polL);
    }
    int t1 = t + q;
    if (t1 < tEnd && lane < 16) {
        int2 ed = ldg_idx_ef(&g_bedge[t1 * 16 + lane], polF);
        sv1 = ed.x; dv1 = ed.y;
    }

    for (;;) {
        uint4 uA1, uB1;
        if (t1 < tEnd) {
            int sA = __shfl_sync(0xffffffffu, sv1, nq);
            int sB = __shfl_sync(0xffffffffu, sv1, nq + 8);
            uA1 = ldg_row_el(h + (size_t)sA * DD + 8 * p, polL);
            uB1 = ldg_row_el(h + (size_t)sB * DD + 8 * p, polL);
        }
        const int t2 = t1 + q;
        int sv2 = 0, dv2 = 0;
        if (t2 < tEnd && lane < 16) {
            int2 ed = ldg_idx_ef(&g_bedge[t2 * 16 + lane], polF);
            sv2 = ed.x; dv2 = ed.y;
        }

        unsigned A0[4], A1[4];
        if (RELU) {
            A0[0] = relu_u(uA0.x); A0[1] = relu_u(uB0.x);
            A0[2] = relu_u(uA0.y); A0[3] = relu_u(uB0.y);
            A1[0] = relu_u(uA0.z); A1[1] = relu_u(uB0.z);
            A1[2] = relu_u(uA0.w); A1[3] = relu_u(uB0.w);
        } else {
            A0[0] = uA0.x; A0[1] = uB0.x; A0[2] = uA0.y; A0[3] = uB0.y;
            A1[0] = uA0.z; A1[1] = uB0.z; A1[2] = uA0.w; A1[3] = uB0.w;
        }

        float acc[4][4];
#pragma unroll
        for (int g = 0; g < 4; g++) {
            acc[g][0] = 0.f; acc[g][1] = 0.f; acc[g][2] = 0.f; acc[g][3] = 0.f;
        }
#pragma unroll
        for (int g = 0; g < 4; g++) {
            mma16816(acc[g], A0, bf[g][0]);
            mma16816(acc[g], A1, bf[g][1]);
        }

        const int dA = __shfl_sync(0xffffffffu, dv0, nq);
        const int dB = __shfl_sync(0xffffffffu, dv0, nq + 8);

        __half* pA = agg + (size_t)dA * DD + 8 * p;
        RED16(pA, pack_h2(acc[0][0], acc[0][1]), pack_h2(acc[1][0], acc[1][1]),
                  pack_h2(acc[2][0], acc[2][1]), pack_h2(acc[3][0], acc[3][1]));
        __half* pB = agg + (size_t)dB * DD + 8 * p;
        RED16(pB, pack_h2(acc[0][2], acc[0][3]), pack_h2(acc[1][2], acc[1][3]),
                  pack_h2(acc[2][2], acc[2][3]), pack_h2(acc[3][2], acc[3][3]));

        if (t1 >= tEnd) break;
        t = t1; t1 = t2;
        dv0 = dv1; sv1 = sv2; dv1 = dv2;
        uA0 = uA1; uB0 = uB1;
    }
}

// ---------------------------------------------------------------------------
// mean: out[m][f(j)] = mean_a relu(agg[m*32+a][j])  (agg in layout L)
// ---------------------------------------------------------------------------
__global__ void mean_kernel(const __half* __restrict__ agg,
                            float* __restrict__ out, int M)
{
    int j = threadIdx.x & 31;
    int m = (blockIdx.x * blockDim.x + threadIdx.x) >> 5;
    if (m >= M) return;
    float s = 0.0f;
#pragma unroll
    for (int a = 0; a < 32; a++)
        s += fmaxf(__half2float(agg[((size_t)m * 32 + a) * DD + j]), 0.0f);
    const int f = 2 * (j >> 3) + 8 * ((j & 7) >> 1) + (j & 1);
    out[(size_t)m * DD + f] = s * (1.0f / 32.0f);
}

// ---------------------------------------------------------------------------
extern "C" void kernel_launch(void* const* d_in, const int* in_sizes, int n_in,
                              void* d_out, int out_size)
{
    const float* x    = (const float*)d_in[0];
    const float* W    = (const float*)d_in[1];
    const float* Wl   = (const float*)d_in[2];
    const float* bias = (const float*)d_in[3];
    const int*   src  = (const int*)d_in[4];
    const int*   dst  = (const int*)d_in[5];
    const int*   et   = (const int*)d_in[6];
    float* out = (float*)d_out;

    const int N = in_sizes[0] / DD;
    const int E = in_sizes[4];
    const int M = out_size / DD;
    const int nTilesN = N / 16;
    const int nb = (E + HIST_CHUNK - 1) / HIST_CHUNK;

    void *hP = nullptr, *aP = nullptr, *bP = nullptr;
    cudaGetSymbolAddress(&hP, g_h16);
    cudaGetSymbolAddress(&aP, g_aggA);
    cudaGetSymbolAddress(&bP, g_aggB);
    __half* h16  = (__half*)hP;
    __half* aggA = (__half*)aP;
    __half* aggB = (__half*)bP;

    // Side stream + events: created once on the uncaptured correctness call,
    // then reused inside graph capture (fork/join pattern).
    static cudaStream_t sB = nullptr;
    static cudaEvent_t eFork, eP1;
    if (!sB) {
        cudaStreamCreateWithFlags(&sB, cudaStreamNonBlocking);
        cudaEventCreateWithFlags(&eFork, cudaEventDisableTiming);
        cudaEventCreateWithFlags(&eP1,   cudaEventDisableTiming);
    }

    const int projBlocks = 1024;
    const int edgeBlocks = 8192;   // 4 quarters x 2048
    const int meanBlocks = (M * 32 + 255) / 256;

    // ---- Fork: proj1 on side stream, binning on default (independent) ----
    cudaEventRecord(eFork, 0);
    cudaStreamWaitEvent(sB, eFork, 0);
    proj1_kernel<<<projBlocks, 256, 0, sB>>>(x, Wl, bias, h16, aggA, nTilesN);
    cudaEventRecord(eP1, sB);

    bin_hist_kernel<<<nb, 256>>>(et, E);
    bin_scan_kernel<<<1, 1024>>>(nb, N);
    bin_scatter_kernel<<<nb, 256>>>(src, dst, et, E);

    // ---- Join, then Layer 1 edge ----
    cudaStreamWaitEvent(0, eP1, 0);
    edge_mma_kernel<false><<<edgeBlocks, 256>>>(h16, W, aggA);

    // ---- Layer 2 ----
    proj2_kernel<<<projBlocks, 256>>>(aggA, Wl, bias, aggB, nTilesN);
    edge_mma_kernel<true><<<edgeBlocks, 256>>>(aggA, W, aggB);

    // ---- Per-molecule mean (relu fused) ----
    mean_kernel<<<meanBlocks, 256>>>(aggB, out, M);
}